// round 12
// baseline (speedup 1.0000x reference)
#include <cuda_runtime.h>

#define BATCH 2048
#define SEQ   128
#define F     512
#define NACT  128
#define GN_EPS 1e-5f

typedef unsigned long long u64;

// packed f32x2 helpers (sm_90+ PTX; ptxas never auto-fuses FFMA2)
#define FMA2(d, a, b) asm("fma.rn.f32x2 %0, %1, %2, %0;" : "+l"(d) : "l"(a), "l"(b))
#define DUP2(d, s)    asm("mov.b64 %0, {%1, %1};" : "=l"(d) : "r"(__float_as_uint(s)))
#define UNPK(lo, hi, d) asm("mov.b64 {%0, %1}, %2;" : "=f"(lo), "=f"(hi) : "l"(d))

// ---------------- scratch (no allocations allowed) ----------------
__device__ float g_p_avg[BATCH * F];
__device__ float g_e_avg[BATCH * F];
__device__ float g_p_embed[BATCH * F];
__device__ int   g_off[NACT + 1];
__device__ int   g_perm[BATCH];

// ---------------- K0: zero atomic targets ----------------
__global__ void k_zero(float* __restrict__ out)
{
    const int idx = blockIdx.x * 256 + threadIdx.x;
    const int n_out4 = (BATCH * F * 2) / 4;
    if (idx < n_out4)
        ((float4*)out)[idx] = make_float4(0.f, 0.f, 0.f, 0.f);
    else
        ((float4*)g_p_embed)[idx - n_out4] = make_float4(0.f, 0.f, 0.f, 0.f);
}

// ---------------- K1: masked mean over seq + GroupNorm(1,1) ----------------
__global__ void k_reduce_gn(const float* __restrict__ pre,
                            const float* __restrict__ eff,
                            const float* __restrict__ gamma,
                            const float* __restrict__ beta)
{
    const int b = blockIdx.x;
    const float* src = (blockIdx.y == 0) ? pre : eff;
    float* dst       = (blockIdx.y == 0) ? g_p_avg : g_e_avg;

    const int t = threadIdx.x;  // 0..127
    const float4* row = (const float4*)(src + (size_t)b * SEQ * F);

    float4 sum = make_float4(0.f, 0.f, 0.f, 0.f);
    int cx = 0, cy = 0, cz = 0, cw = 0;

    #pragma unroll 8
    for (int s = 0; s < SEQ; s++) {
        float4 v = row[s * (F / 4) + t];
        sum.x += v.x; sum.y += v.y; sum.z += v.z; sum.w += v.w;
        cx += (v.x != 0.0f); cy += (v.y != 0.0f);
        cz += (v.z != 0.0f); cw += (v.w != 0.0f);
    }

    float4 m;
    m.x = sum.x / (float)cx;
    m.y = sum.y / (float)cy;
    m.z = sum.z / (float)cz;
    m.w = sum.w / (float)cw;

    float ls = m.x + m.y + m.z + m.w;
    float lq = m.x * m.x + m.y * m.y + m.z * m.z + m.w * m.w;

    __shared__ float s1[128], s2[128];
    s1[t] = ls; s2[t] = lq;
    __syncthreads();
    #pragma unroll
    for (int o = 64; o > 0; o >>= 1) {
        if (t < o) { s1[t] += s1[t + o]; s2[t] += s2[t + o]; }
        __syncthreads();
    }
    const float mu  = s1[0] * (1.0f / F);
    const float var = s2[0] * (1.0f / F) - mu * mu;
    const float r   = rsqrtf(var + GN_EPS) * gamma[0];
    const float be  = beta[0];

    float4 o4;
    o4.x = (m.x - mu) * r + be;
    o4.y = (m.y - mu) * r + be;
    o4.z = (m.z - mu) * r + be;
    o4.w = (m.w - mu) * r + be;
    ((float4*)(dst + (size_t)b * F))[t] = o4;
}

// ---------------- K2: group batch indices by action ----------------
__global__ void k_group(const int* __restrict__ action)
{
    __shared__ int s_cnt[NACT];
    __shared__ int s_cur[NACT];
    const int t = threadIdx.x;
    if (t < NACT) s_cnt[t] = 0;
    __syncthreads();
    for (int i = t; i < BATCH; i += 256)
        atomicAdd(&s_cnt[action[i]], 1);
    __syncthreads();
    if (t == 0) {
        int acc = 0;
        for (int a = 0; a < NACT; a++) {
            g_off[a] = acc; s_cur[a] = acc; acc += s_cnt[a];
        }
        g_off[NACT] = acc;
    }
    __syncthreads();
    for (int i = t; i < BATCH; i += 256) {
        int pos = atomicAdd(&s_cur[action[i]], 1);
        g_perm[pos] = i;
    }
}

// ---------------- K3: embed GEMMs, K-split 2 + atomics, FMA2 core ----------------
// grid (F/64, BATCH/128, 4), 256 threads. z = src*2 + kc.
// Tile 128m x 64i, Kt=16, 8x4 microtile packed as 4 m-pairs x 4 cols.
#define EKC 256
__global__ void __launch_bounds__(256)
k_embed(const float* __restrict__ pw, const float* __restrict__ pb,
        const float* __restrict__ ew, const float* __restrict__ eb,
        float* __restrict__ dout)
{
    const int srcsel = blockIdx.z >> 1;
    const int kc     = blockIdx.z & 1;
    const int k0g    = kc * EKC;

    const float* A; const float* Wt; const float* bias; float* C;
    if (srcsel == 0) { A = g_p_avg; Wt = pw; bias = pb; C = g_p_embed; }
    else             { A = g_e_avg; Wt = ew; bias = eb; C = dout + (size_t)BATCH * F; }

    const int i0 = blockIdx.x * 64;
    const int b0 = blockIdx.y * 128;

    __shared__ float As[16][128];
    __shared__ float Bs[16][64];

    const int t  = threadIdx.x;
    const int tx = t & 15;
    const int ty = t >> 4;

    const int lr = t >> 2;
    const int lk = (t & 3) * 4;

    u64 acc2[4][4];   // [m-pair][col]; lane0 = row 2p, lane1 = row 2p+1
    #pragma unroll
    for (int p = 0; p < 4; p++)
        #pragma unroll
        for (int c = 0; c < 4; c++) acc2[p][c] = 0ULL;

    float4 a0 = *(const float4*)(A  + (size_t)(b0 + lr)      * F + k0g + lk);
    float4 a1 = *(const float4*)(A  + (size_t)(b0 + lr + 64) * F + k0g + lk);
    float4 bv = *(const float4*)(Wt + (size_t)(i0 + lr)      * F + k0g + lk);

    for (int k0 = 0; k0 < EKC; k0 += 16) {
        As[lk + 0][lr]      = a0.x; As[lk + 1][lr]      = a0.y;
        As[lk + 2][lr]      = a0.z; As[lk + 3][lr]      = a0.w;
        As[lk + 0][lr + 64] = a1.x; As[lk + 1][lr + 64] = a1.y;
        As[lk + 2][lr + 64] = a1.z; As[lk + 3][lr + 64] = a1.w;
        Bs[lk + 0][lr] = bv.x; Bs[lk + 1][lr] = bv.y;
        Bs[lk + 2][lr] = bv.z; Bs[lk + 3][lr] = bv.w;
        __syncthreads();

        if (k0 + 16 < EKC) {
            a0 = *(const float4*)(A  + (size_t)(b0 + lr)      * F + k0g + k0 + 16 + lk);
            a1 = *(const float4*)(A  + (size_t)(b0 + lr + 64) * F + k0g + k0 + 16 + lk);
            bv = *(const float4*)(Wt + (size_t)(i0 + lr)      * F + k0g + k0 + 16 + lk);
        }

        #pragma unroll
        for (int kk = 0; kk < 16; kk++) {
            // 4 m-pairs, packed for free in smem (rows adjacent)
            ulonglong2 apA = *(const ulonglong2*)&As[kk][ty * 8];
            ulonglong2 apB = *(const ulonglong2*)&As[kk][ty * 8 + 4];
            float4 rb = *(const float4*)&Bs[kk][tx * 4];
            u64 bd0, bd1, bd2, bd3;
            DUP2(bd0, rb.x); DUP2(bd1, rb.y); DUP2(bd2, rb.z); DUP2(bd3, rb.w);

            FMA2(acc2[0][0], apA.x, bd0); FMA2(acc2[0][1], apA.x, bd1);
            FMA2(acc2[0][2], apA.x, bd2); FMA2(acc2[0][3], apA.x, bd3);
            FMA2(acc2[1][0], apA.y, bd0); FMA2(acc2[1][1], apA.y, bd1);
            FMA2(acc2[1][2], apA.y, bd2); FMA2(acc2[1][3], apA.y, bd3);
            FMA2(acc2[2][0], apB.x, bd0); FMA2(acc2[2][1], apB.x, bd1);
            FMA2(acc2[2][2], apB.x, bd2); FMA2(acc2[2][3], apB.x, bd3);
            FMA2(acc2[3][0], apB.y, bd0); FMA2(acc2[3][1], apB.y, bd1);
            FMA2(acc2[3][2], apB.y, bd2); FMA2(acc2[3][3], apB.y, bd3);
        }
        __syncthreads();
    }

    float bsv[4] = { 0.f, 0.f, 0.f, 0.f };
    if (kc == 0) {
        #pragma unroll
        for (int c = 0; c < 4; c++) bsv[c] = bias[i0 + tx * 4 + c];
    }

    #pragma unroll
    for (int p = 0; p < 4; p++) {
        float lo[4], hi[4];
        #pragma unroll
        for (int c = 0; c < 4; c++) UNPK(lo[c], hi[c], acc2[p][c]);
        float* o0 = C + (size_t)(b0 + ty * 8 + 2 * p)     * F + i0 + tx * 4;
        float* o1 = C + (size_t)(b0 + ty * 8 + 2 * p + 1) * F + i0 + tx * 4;
        #pragma unroll
        for (int c = 0; c < 4; c++) {
            atomicAdd(o0 + c, lo[c] + bsv[c]);
            atomicAdd(o1 + c, hi[c] + bsv[c]);
        }
    }
}

// ---------------- K4: per-action gather GEMM, K-split 8 + atomics, FMA2 core ----
// grid (NACT, 8 kchunks, 2 ihalves), 256 threads.
// CTA tile: 256i x 16m x 64k. Micro 2m x 8i packed as 2m x 4 col-pairs.
#define KC 64
__global__ void __launch_bounds__(256)
k_action(const float* __restrict__ W, float* __restrict__ dout)
{
    const int a   = blockIdx.x;
    const int kc  = blockIdx.y;        // k chunk 0..7
    const int ih  = blockIdx.z;        // i half
    const int i0  = ih * 256;
    const int k0g = kc * KC;
    const int beg = g_off[a];
    const int n   = g_off[a + 1] - beg;

    __shared__ float As[16][KC + 4];   // P rows [m][k_local]
    __shared__ float Bs[8][256];       // W chunk [k][i]

    const int t  = threadIdx.x;        // 0..255
    const int ti = t & 31;
    const int tm = t >> 5;
    const int ia = ti * 4;
    const int ib = ti * 4 + 128;

    const float* Wa = W + (size_t)a * F * F + (size_t)i0 * F + k0g;

    for (int m0 = 0; m0 < n; m0 += 16) {
        // ---- stage 16 P rows (local K window) ----
        {
            const int m  = t >> 4;
            const int c4 = t & 15;
            const int mi = (m0 + m < n) ? (m0 + m) : m0;   // clamp; never written out
            const float* src = g_p_embed + (size_t)g_perm[beg + mi] * F + k0g;
            *(float4*)&As[m][c4 * 4] = *(const float4*)(src + c4 * 4);
        }

        u64 acc2[2][4];
        #pragma unroll
        for (int r = 0; r < 2; r++)
            #pragma unroll
            for (int c = 0; c < 4; c++) acc2[r][c] = 0ULL;

        float4 w0 = *(const float4*)(Wa + (size_t)t * F + 0);
        float4 w1 = *(const float4*)(Wa + (size_t)t * F + 4);
        __syncthreads();   // As staged

        for (int c = 0; c < KC / 8; c++) {
            Bs[0][t] = w0.x; Bs[1][t] = w0.y; Bs[2][t] = w0.z; Bs[3][t] = w0.w;
            Bs[4][t] = w1.x; Bs[5][t] = w1.y; Bs[6][t] = w1.z; Bs[7][t] = w1.w;
            __syncthreads();

            if (c + 1 < KC / 8) {
                const int kn = (c + 1) * 8;
                w0 = *(const float4*)(Wa + (size_t)t * F + kn);
                w1 = *(const float4*)(Wa + (size_t)t * F + kn + 4);
            }

            const int kb = c * 8;
            #pragma unroll
            for (int kk = 0; kk < 8; kk++) {
                u64 a0d, a1d;
                DUP2(a0d, As[tm * 2 + 0][kb + kk]);
                DUP2(a1d, As[tm * 2 + 1][kb + kk]);
                ulonglong2 bp0 = *(const ulonglong2*)&Bs[kk][ia];
                ulonglong2 bp1 = *(const ulonglong2*)&Bs[kk][ib];
                FMA2(acc2[0][0], a0d, bp0.x); FMA2(acc2[0][1], a0d, bp0.y);
                FMA2(acc2[0][2], a0d, bp1.x); FMA2(acc2[0][3], a0d, bp1.y);
                FMA2(acc2[1][0], a1d, bp0.x); FMA2(acc2[1][1], a1d, bp0.y);
                FMA2(acc2[1][2], a1d, bp1.x); FMA2(acc2[1][3], a1d, bp1.y);
            }
            __syncthreads();
        }

        // accumulate partials into output
        #pragma unroll
        for (int r = 0; r < 2; r++) {
            const int m = m0 + tm * 2 + r;
            if (m < n) {
                float* obase = dout + (size_t)g_perm[beg + m] * F + i0;
                float lo, hi;
                UNPK(lo, hi, acc2[r][0]); atomicAdd(obase + ia + 0, lo); atomicAdd(obase + ia + 1, hi);
                UNPK(lo, hi, acc2[r][1]); atomicAdd(obase + ia + 2, lo); atomicAdd(obase + ia + 3, hi);
                UNPK(lo, hi, acc2[r][2]); atomicAdd(obase + ib + 0, lo); atomicAdd(obase + ib + 1, hi);
                UNPK(lo, hi, acc2[r][3]); atomicAdd(obase + ib + 2, lo); atomicAdd(obase + ib + 3, hi);
            }
        }
    }
}

// ---------------- launch ----------------
extern "C" void kernel_launch(void* const* d_in, const int* in_sizes, int n_in,
                              void* d_out, int out_size)
{
    const float* pre   = (const float*)d_in[0];
    const float* eff   = (const float*)d_in[1];
    const int*   act   = (const int*)  d_in[2];
    const float* W     = (const float*)d_in[3];
    const float* pw    = (const float*)d_in[4];
    const float* pb    = (const float*)d_in[5];
    const float* ew    = (const float*)d_in[6];
    const float* eb    = (const float*)d_in[7];
    const float* gamma = (const float*)d_in[8];
    const float* beta  = (const float*)d_in[9];
    float* out = (float*)d_out;

    k_zero<<<(BATCH * F * 3) / (256 * 4), 256>>>(out);
    k_group<<<1, 256>>>(act);
    k_reduce_gn<<<dim3(BATCH, 2), 128>>>(pre, eff, gamma, beta);
    k_embed<<<dim3(F / 64, BATCH / 128, 4), 256>>>(pw, pb, ew, eb, out);
    k_action<<<dim3(NACT, 8, 2), 256>>>(W, out);
}

// round 14
// speedup vs baseline: 1.0167x; 1.0167x over previous
#include <cuda_runtime.h>

#define BATCH 2048
#define SEQ   128
#define F     512
#define NACT  128
#define GN_EPS 1e-5f

typedef unsigned long long u64;

// packed f32x2 helpers
#define FMA2(d, a, b) asm("fma.rn.f32x2 %0, %1, %2, %0;" : "+l"(d) : "l"(a), "l"(b))
#define DUP2(d, s)    asm("mov.b64 %0, {%1, %1};" : "=l"(d) : "r"(__float_as_uint(s)))
#define UNPK(lo, hi, d) asm("mov.b64 {%0, %1}, %2;" : "=f"(lo), "=f"(hi) : "l"(d))

// ---------------- scratch (no allocations allowed) ----------------
__device__ float g_p_avg[BATCH * F];
__device__ float g_e_avg[BATCH * F];
__device__ float g_p_embed[BATCH * F];
__device__ int   g_off[NACT + 1];
__device__ int   g_perm[BATCH];

// ---------------- K0: zero k_action's atomic target (out first half) ----------
__global__ void k_zero(float* __restrict__ out)
{
    ((float4*)out)[blockIdx.x * 256 + threadIdx.x] =
        make_float4(0.f, 0.f, 0.f, 0.f);
}

// ---------------- K1: masked mean over seq + GroupNorm(1,1) ----------------
__global__ void k_reduce_gn(const float* __restrict__ pre,
                            const float* __restrict__ eff,
                            const float* __restrict__ gamma,
                            const float* __restrict__ beta)
{
    const int b = blockIdx.x;
    const float* src = (blockIdx.y == 0) ? pre : eff;
    float* dst       = (blockIdx.y == 0) ? g_p_avg : g_e_avg;

    const int t = threadIdx.x;  // 0..127
    const float4* row = (const float4*)(src + (size_t)b * SEQ * F);

    float4 sum = make_float4(0.f, 0.f, 0.f, 0.f);
    int cx = 0, cy = 0, cz = 0, cw = 0;

    #pragma unroll 8
    for (int s = 0; s < SEQ; s++) {
        float4 v = row[s * (F / 4) + t];
        sum.x += v.x; sum.y += v.y; sum.z += v.z; sum.w += v.w;
        cx += (v.x != 0.0f); cy += (v.y != 0.0f);
        cz += (v.z != 0.0f); cw += (v.w != 0.0f);
    }

    float4 m;
    m.x = sum.x / (float)cx;
    m.y = sum.y / (float)cy;
    m.z = sum.z / (float)cz;
    m.w = sum.w / (float)cw;

    float ls = m.x + m.y + m.z + m.w;
    float lq = m.x * m.x + m.y * m.y + m.z * m.z + m.w * m.w;

    __shared__ float s1[128], s2[128];
    s1[t] = ls; s2[t] = lq;
    __syncthreads();
    #pragma unroll
    for (int o = 64; o > 0; o >>= 1) {
        if (t < o) { s1[t] += s1[t + o]; s2[t] += s2[t + o]; }
        __syncthreads();
    }
    const float mu  = s1[0] * (1.0f / F);
    const float var = s2[0] * (1.0f / F) - mu * mu;
    const float r   = rsqrtf(var + GN_EPS) * gamma[0];
    const float be  = beta[0];

    float4 o4;
    o4.x = (m.x - mu) * r + be;
    o4.y = (m.y - mu) * r + be;
    o4.z = (m.z - mu) * r + be;
    o4.w = (m.w - mu) * r + be;
    ((float4*)(dst + (size_t)b * F))[t] = o4;
}

// ---------------- K2: group batch indices by action ----------------
__global__ void k_group(const int* __restrict__ action)
{
    __shared__ int s_cnt[NACT];
    __shared__ int s_cur[NACT];
    const int t = threadIdx.x;
    if (t < NACT) s_cnt[t] = 0;
    __syncthreads();
    for (int i = t; i < BATCH; i += 256)
        atomicAdd(&s_cnt[action[i]], 1);
    __syncthreads();
    if (t == 0) {
        int acc = 0;
        for (int a = 0; a < NACT; a++) {
            g_off[a] = acc; s_cur[a] = acc; acc += s_cnt[a];
        }
        g_off[NACT] = acc;
    }
    __syncthreads();
    for (int i = t; i < BATCH; i += 256) {
        int pos = atomicAdd(&s_cur[action[i]], 1);
        g_perm[pos] = i;
    }
}

// ---------------- K3: embed GEMMs (R10 proven version, direct store) ----------
// grid (F/64, BATCH/128, 2), 256 threads. Tile 128m x 64i, Kt=16, 8x4 microtile.
__global__ void __launch_bounds__(256)
k_embed(const float* __restrict__ pw, const float* __restrict__ pb,
        const float* __restrict__ ew, const float* __restrict__ eb,
        float* __restrict__ dout)
{
    const float* A; const float* Wt; const float* bias; float* C;
    if (blockIdx.z == 0) { A = g_p_avg; Wt = pw; bias = pb; C = g_p_embed; }
    else                 { A = g_e_avg; Wt = ew; bias = eb; C = dout + (size_t)BATCH * F; }

    const int i0 = blockIdx.x * 64;
    const int b0 = blockIdx.y * 128;

    __shared__ float As[16][128];
    __shared__ float Bs[16][64];

    const int t  = threadIdx.x;
    const int tx = t & 15;
    const int ty = t >> 4;

    const int lr = t >> 2;
    const int lk = (t & 3) * 4;

    float acc[8][4];
    #pragma unroll
    for (int r = 0; r < 8; r++)
        #pragma unroll
        for (int c = 0; c < 4; c++) acc[r][c] = 0.f;

    float4 a0 = *(const float4*)(A  + (size_t)(b0 + lr)      * F + lk);
    float4 a1 = *(const float4*)(A  + (size_t)(b0 + lr + 64) * F + lk);
    float4 bv = *(const float4*)(Wt + (size_t)(i0 + lr)      * F + lk);

    for (int k0 = 0; k0 < F; k0 += 16) {
        As[lk + 0][lr]      = a0.x; As[lk + 1][lr]      = a0.y;
        As[lk + 2][lr]      = a0.z; As[lk + 3][lr]      = a0.w;
        As[lk + 0][lr + 64] = a1.x; As[lk + 1][lr + 64] = a1.y;
        As[lk + 2][lr + 64] = a1.z; As[lk + 3][lr + 64] = a1.w;
        Bs[lk + 0][lr] = bv.x; Bs[lk + 1][lr] = bv.y;
        Bs[lk + 2][lr] = bv.z; Bs[lk + 3][lr] = bv.w;
        __syncthreads();

        if (k0 + 16 < F) {
            a0 = *(const float4*)(A  + (size_t)(b0 + lr)      * F + k0 + 16 + lk);
            a1 = *(const float4*)(A  + (size_t)(b0 + lr + 64) * F + k0 + 16 + lk);
            bv = *(const float4*)(Wt + (size_t)(i0 + lr)      * F + k0 + 16 + lk);
        }

        #pragma unroll
        for (int kk = 0; kk < 16; kk++) {
            float4 ra0 = *(const float4*)&As[kk][ty * 8];
            float4 ra1 = *(const float4*)&As[kk][ty * 8 + 4];
            float4 rb  = *(const float4*)&Bs[kk][tx * 4];
            float am[8] = { ra0.x, ra0.y, ra0.z, ra0.w, ra1.x, ra1.y, ra1.z, ra1.w };
            float bn[4] = { rb.x, rb.y, rb.z, rb.w };
            #pragma unroll
            for (int r = 0; r < 8; r++)
                #pragma unroll
                for (int c = 0; c < 4; c++)
                    acc[r][c] += am[r] * bn[c];
        }
        __syncthreads();
    }

    float bsv[4];
    #pragma unroll
    for (int c = 0; c < 4; c++) bsv[c] = bias[i0 + tx * 4 + c];

    #pragma unroll
    for (int r = 0; r < 8; r++) {
        float4 o;
        o.x = acc[r][0] + bsv[0];
        o.y = acc[r][1] + bsv[1];
        o.z = acc[r][2] + bsv[2];
        o.w = acc[r][3] + bsv[3];
        *(float4*)(C + (size_t)(b0 + ty * 8 + r) * F + i0 + tx * 4) = o;
    }
}

// ---------------- K4: per-action gather GEMM, K-split 4, double-buffered ------
// out[b][i] += sum_{j in kc} W[a][i][j] * p_embed[b][j]
// grid (NACT, 4 kchunks, 2 ihalves), 256 threads.
// CTA tile: 256i x 16m x 128k. Subchunk 16k, Bs double-buffered -> 1 bar/subchunk.
#define KC 128
__global__ void __launch_bounds__(256)
k_action(const float* __restrict__ W, float* __restrict__ dout)
{
    const int a   = blockIdx.x;
    const int kc  = blockIdx.y;        // k chunk 0..3
    const int ih  = blockIdx.z;        // i half
    const int i0  = ih * 256;
    const int k0g = kc * KC;
    const int beg = g_off[a];
    const int n   = g_off[a + 1] - beg;

    __shared__ float As[16][KC];       // P rows [m][k_local]   8 KB
    __shared__ float Bs[2][16][256];   // W subchunks [k][i]   32 KB

    const int t  = threadIdx.x;        // 0..255
    const int ti = t & 31;
    const int tm = t >> 5;             // warp-uniform m-group
    const int ia = ti * 4;
    const int ib = ti * 4 + 128;

    // this thread's W row (one row per thread, k window of this CTA)
    const float* Wrow = W + (size_t)a * F * F + (size_t)(i0 + t) * F + k0g;

    const int mS = t >> 4;             // staging: P row 0..15
    const int c4 = t & 15;             // staging: float4 lane (x2)

    for (int m0 = 0; m0 < n; m0 += 16) {
        // prefetch W subchunk 0 (16 k values = 4 float4 per thread-row)
        float4 w0 = *(const float4*)(Wrow + 0);
        float4 w1 = *(const float4*)(Wrow + 4);
        float4 w2 = *(const float4*)(Wrow + 8);
        float4 w3 = *(const float4*)(Wrow + 12);

        // stage 16 P rows (local K window)
        {
            const int mi = (m0 + mS < n) ? (m0 + mS) : m0;   // clamp; never written out
            const float* src = g_p_embed + (size_t)g_perm[beg + mi] * F + k0g;
            float4 p0 = *(const float4*)(src + c4 * 4);
            float4 p1 = *(const float4*)(src + (c4 + 16) * 4);
            *(float4*)&As[mS][c4 * 4]        = p0;
            *(float4*)&As[mS][(c4 + 16) * 4] = p1;
        }

        // store W subchunk 0 into buffer 0
        Bs[0][ 0][t] = w0.x; Bs[0][ 1][t] = w0.y; Bs[0][ 2][t] = w0.z; Bs[0][ 3][t] = w0.w;
        Bs[0][ 4][t] = w1.x; Bs[0][ 5][t] = w1.y; Bs[0][ 6][t] = w1.z; Bs[0][ 7][t] = w1.w;
        Bs[0][ 8][t] = w2.x; Bs[0][ 9][t] = w2.y; Bs[0][10][t] = w2.z; Bs[0][11][t] = w2.w;
        Bs[0][12][t] = w3.x; Bs[0][13][t] = w3.y; Bs[0][14][t] = w3.z; Bs[0][15][t] = w3.w;

        u64 acc2[2][4];
        #pragma unroll
        for (int r = 0; r < 2; r++)
            #pragma unroll
            for (int c = 0; c < 4; c++) acc2[r][c] = 0ULL;

        __syncthreads();   // As + Bs[0] visible

        for (int c = 0; c < KC / 16; c++) {
            const int cur  = c & 1;
            const bool more = (c + 1 < KC / 16);

            // issue next subchunk's loads before compute (overlap DRAM latency)
            if (more) {
                const int kn = (c + 1) * 16;
                w0 = *(const float4*)(Wrow + kn + 0);
                w1 = *(const float4*)(Wrow + kn + 4);
                w2 = *(const float4*)(Wrow + kn + 8);
                w3 = *(const float4*)(Wrow + kn + 12);
            }

            const int kb = c * 16;
            #pragma unroll
            for (int kk = 0; kk < 16; kk++) {
                u64 a0d, a1d;
                DUP2(a0d, As[tm * 2 + 0][kb + kk]);
                DUP2(a1d, As[tm * 2 + 1][kb + kk]);
                ulonglong2 bp0 = *(const ulonglong2*)&Bs[cur][kk][ia];
                ulonglong2 bp1 = *(const ulonglong2*)&Bs[cur][kk][ib];
                FMA2(acc2[0][0], a0d, bp0.x); FMA2(acc2[0][1], a0d, bp0.y);
                FMA2(acc2[0][2], a0d, bp1.x); FMA2(acc2[0][3], a0d, bp1.y);
                FMA2(acc2[1][0], a1d, bp0.x); FMA2(acc2[1][1], a1d, bp0.y);
                FMA2(acc2[1][2], a1d, bp1.x); FMA2(acc2[1][3], a1d, bp1.y);
            }

            if (more) {
                const int nb = cur ^ 1;
                Bs[nb][ 0][t] = w0.x; Bs[nb][ 1][t] = w0.y; Bs[nb][ 2][t] = w0.z; Bs[nb][ 3][t] = w0.w;
                Bs[nb][ 4][t] = w1.x; Bs[nb][ 5][t] = w1.y; Bs[nb][ 6][t] = w1.z; Bs[nb][ 7][t] = w1.w;
                Bs[nb][ 8][t] = w2.x; Bs[nb][ 9][t] = w2.y; Bs[nb][10][t] = w2.z; Bs[nb][11][t] = w2.w;
                Bs[nb][12][t] = w3.x; Bs[nb][13][t] = w3.y; Bs[nb][14][t] = w3.z; Bs[nb][15][t] = w3.w;
            }
            __syncthreads();   // buffer flip (also protects As at last subchunk)
        }

        // accumulate partials into output
        #pragma unroll
        for (int r = 0; r < 2; r++) {
            const int m = m0 + tm * 2 + r;
            if (m < n) {
                float* obase = dout + (size_t)g_perm[beg + m] * F + i0;
                float lo, hi;
                UNPK(lo, hi, acc2[r][0]); atomicAdd(obase + ia + 0, lo); atomicAdd(obase + ia + 1, hi);
                UNPK(lo, hi, acc2[r][1]); atomicAdd(obase + ia + 2, lo); atomicAdd(obase + ia + 3, hi);
                UNPK(lo, hi, acc2[r][2]); atomicAdd(obase + ib + 0, lo); atomicAdd(obase + ib + 1, hi);
                UNPK(lo, hi, acc2[r][3]); atomicAdd(obase + ib + 2, lo); atomicAdd(obase + ib + 3, hi);
            }
        }
    }
}

// ---------------- launch (serial, capture-safe) ----------------
extern "C" void kernel_launch(void* const* d_in, const int* in_sizes, int n_in,
                              void* d_out, int out_size)
{
    const float* pre   = (const float*)d_in[0];
    const float* eff   = (const float*)d_in[1];
    const int*   act   = (const int*)  d_in[2];
    const float* W     = (const float*)d_in[3];
    const float* pw    = (const float*)d_in[4];
    const float* pb    = (const float*)d_in[5];
    const float* ew    = (const float*)d_in[6];
    const float* eb    = (const float*)d_in[7];
    const float* gamma = (const float*)d_in[8];
    const float* beta  = (const float*)d_in[9];
    float* out = (float*)d_out;

    k_zero<<<(BATCH * F) / (256 * 4), 256>>>(out);   // out first half only
    k_group<<<1, 256>>>(act);
    k_reduce_gn<<<dim3(BATCH, 2), 128>>>(pre, eff, gamma, beta);
    k_embed<<<dim3(F / 64, BATCH / 128, 2), 256>>>(pw, pb, ew, eb, out);
    k_action<<<dim3(NACT, 4, 2), 256>>>(W, out);
}

// round 17
// speedup vs baseline: 1.0216x; 1.0048x over previous
#include <cuda_runtime.h>

#define BATCH 2048
#define SEQ   128
#define F     512
#define NACT  128
#define GN_EPS 1e-5f

typedef unsigned long long u64;

// packed f32x2 helpers
#define FMA2(d, a, b) asm("fma.rn.f32x2 %0, %1, %2, %0;" : "+l"(d) : "l"(a), "l"(b))
#define DUP2(d, s)    asm("mov.b64 %0, {%1, %1};" : "=l"(d) : "r"(__float_as_uint(s)))
#define UNPK(lo, hi, d) asm("mov.b64 {%0, %1}, %2;" : "=f"(lo), "=f"(hi) : "l"(d))

// ---------------- scratch (no allocations allowed) ----------------
__device__ float g_p_avg[BATCH * F];
__device__ float g_e_avg[BATCH * F];
__device__ float g_p_embed[BATCH * F];
__device__ int   g_off[NACT + 1];
__device__ int   g_perm[BATCH];
__device__ int   g_chunks[256];   // (action << 16) | m0
__device__ int   g_nchunks;

// ---------------- K0: zero k_action's atomic target (out first half) ----------
__global__ void k_zero(float* __restrict__ out)
{
    ((float4*)out)[blockIdx.x * 256 + threadIdx.x] =
        make_float4(0.f, 0.f, 0.f, 0.f);
}

// ---------------- K1: masked mean over seq + GroupNorm(1,1) ----------------
__global__ void k_reduce_gn(const float* __restrict__ pre,
                            const float* __restrict__ eff,
                            const float* __restrict__ gamma,
                            const float* __restrict__ beta)
{
    const int b = blockIdx.x;
    const float* src = (blockIdx.y == 0) ? pre : eff;
    float* dst       = (blockIdx.y == 0) ? g_p_avg : g_e_avg;

    const int t = threadIdx.x;  // 0..127
    const float4* row = (const float4*)(src + (size_t)b * SEQ * F);

    float4 sum = make_float4(0.f, 0.f, 0.f, 0.f);
    int cx = 0, cy = 0, cz = 0, cw = 0;

    #pragma unroll 8
    for (int s = 0; s < SEQ; s++) {
        float4 v = row[s * (F / 4) + t];
        sum.x += v.x; sum.y += v.y; sum.z += v.z; sum.w += v.w;
        cx += (v.x != 0.0f); cy += (v.y != 0.0f);
        cz += (v.z != 0.0f); cw += (v.w != 0.0f);
    }

    float4 m;
    m.x = sum.x / (float)cx;
    m.y = sum.y / (float)cy;
    m.z = sum.z / (float)cz;
    m.w = sum.w / (float)cw;

    float ls = m.x + m.y + m.z + m.w;
    float lq = m.x * m.x + m.y * m.y + m.z * m.z + m.w * m.w;

    __shared__ float s1[128], s2[128];
    s1[t] = ls; s2[t] = lq;
    __syncthreads();
    #pragma unroll
    for (int o = 64; o > 0; o >>= 1) {
        if (t < o) { s1[t] += s1[t + o]; s2[t] += s2[t + o]; }
        __syncthreads();
    }
    const float mu  = s1[0] * (1.0f / F);
    const float var = s2[0] * (1.0f / F) - mu * mu;
    const float r   = rsqrtf(var + GN_EPS) * gamma[0];
    const float be  = beta[0];

    float4 o4;
    o4.x = (m.x - mu) * r + be;
    o4.y = (m.y - mu) * r + be;
    o4.z = (m.z - mu) * r + be;
    o4.w = (m.w - mu) * r + be;
    ((float4*)(dst + (size_t)b * F))[t] = o4;
}

// ---------------- K2: group batch indices by action + build chunk worklist ----
__global__ void k_group(const int* __restrict__ action)
{
    __shared__ int s_cnt[NACT];
    __shared__ int s_cur[NACT];
    const int t = threadIdx.x;
    if (t < NACT) s_cnt[t] = 0;
    __syncthreads();
    for (int i = t; i < BATCH; i += 256)
        atomicAdd(&s_cnt[action[i]], 1);
    __syncthreads();
    if (t == 0) {
        int acc = 0;
        int nc = 0;
        for (int a = 0; a < NACT; a++) {
            g_off[a] = acc; s_cur[a] = acc;
            const int na = s_cnt[a];
            acc += na;
            for (int m0 = 0; m0 < na; m0 += 16)
                g_chunks[nc++] = (a << 16) | m0;
        }
        g_off[NACT] = acc;
        g_nchunks = nc;
    }
    __syncthreads();
    for (int i = t; i < BATCH; i += 256) {
        int pos = atomicAdd(&s_cur[action[i]], 1);
        g_perm[pos] = i;
    }
}

// ---------------- K3: embed GEMMs (R10 proven version, direct store) ----------
// grid (F/64, BATCH/128, 2), 256 threads. Tile 128m x 64i, Kt=16, 8x4 microtile.
__global__ void __launch_bounds__(256)
k_embed(const float* __restrict__ pw, const float* __restrict__ pb,
        const float* __restrict__ ew, const float* __restrict__ eb,
        float* __restrict__ dout)
{
    const float* A; const float* Wt; const float* bias; float* C;
    if (blockIdx.z == 0) { A = g_p_avg; Wt = pw; bias = pb; C = g_p_embed; }
    else                 { A = g_e_avg; Wt = ew; bias = eb; C = dout + (size_t)BATCH * F; }

    const int i0 = blockIdx.x * 64;
    const int b0 = blockIdx.y * 128;

    __shared__ float As[16][128];
    __shared__ float Bs[16][64];

    const int t  = threadIdx.x;
    const int tx = t & 15;
    const int ty = t >> 4;

    const int lr = t >> 2;
    const int lk = (t & 3) * 4;

    float acc[8][4];
    #pragma unroll
    for (int r = 0; r < 8; r++)
        #pragma unroll
        for (int c = 0; c < 4; c++) acc[r][c] = 0.f;

    float4 a0 = *(const float4*)(A  + (size_t)(b0 + lr)      * F + lk);
    float4 a1 = *(const float4*)(A  + (size_t)(b0 + lr + 64) * F + lk);
    float4 bv = *(const float4*)(Wt + (size_t)(i0 + lr)      * F + lk);

    for (int k0 = 0; k0 < F; k0 += 16) {
        As[lk + 0][lr]      = a0.x; As[lk + 1][lr]      = a0.y;
        As[lk + 2][lr]      = a0.z; As[lk + 3][lr]      = a0.w;
        As[lk + 0][lr + 64] = a1.x; As[lk + 1][lr + 64] = a1.y;
        As[lk + 2][lr + 64] = a1.z; As[lk + 3][lr + 64] = a1.w;
        Bs[lk + 0][lr] = bv.x; Bs[lk + 1][lr] = bv.y;
        Bs[lk + 2][lr] = bv.z; Bs[lk + 3][lr] = bv.w;
        __syncthreads();

        if (k0 + 16 < F) {
            a0 = *(const float4*)(A  + (size_t)(b0 + lr)      * F + k0 + 16 + lk);
            a1 = *(const float4*)(A  + (size_t)(b0 + lr + 64) * F + k0 + 16 + lk);
            bv = *(const float4*)(Wt + (size_t)(i0 + lr)      * F + k0 + 16 + lk);
        }

        #pragma unroll
        for (int kk = 0; kk < 16; kk++) {
            float4 ra0 = *(const float4*)&As[kk][ty * 8];
            float4 ra1 = *(const float4*)&As[kk][ty * 8 + 4];
            float4 rb  = *(const float4*)&Bs[kk][tx * 4];
            float am[8] = { ra0.x, ra0.y, ra0.z, ra0.w, ra1.x, ra1.y, ra1.z, ra1.w };
            float bn[4] = { rb.x, rb.y, rb.z, rb.w };
            #pragma unroll
            for (int r = 0; r < 8; r++)
                #pragma unroll
                for (int c = 0; c < 4; c++)
                    acc[r][c] += am[r] * bn[c];
        }
        __syncthreads();
    }

    float bsv[4];
    #pragma unroll
    for (int c = 0; c < 4; c++) bsv[c] = bias[i0 + tx * 4 + c];

    #pragma unroll
    for (int r = 0; r < 8; r++) {
        float4 o;
        o.x = acc[r][0] + bsv[0];
        o.y = acc[r][1] + bsv[1];
        o.z = acc[r][2] + bsv[2];
        o.w = acc[r][3] + bsv[3];
        *(float4*)(C + (size_t)(b0 + ty * 8 + r) * F + i0 + tx * 4) = o;
    }
}

// ---------------- K4: gather GEMM over uniform chunk worklist ------------------
// One (action, m0) chunk per CTA: 16m x 256i x 128k, K-split 4 + atomics.
// grid (256 chunks, 4 kchunks, 2 ihalves), 256 threads.
#define KC 128
__global__ void __launch_bounds__(256)
k_action(const float* __restrict__ W, float* __restrict__ dout)
{
    const int c_id = blockIdx.x;
    if (c_id >= g_nchunks) return;
    const int chunk = g_chunks[c_id];
    const int a   = chunk >> 16;
    const int m0  = chunk & 0xFFFF;
    const int kc  = blockIdx.y;
    const int ih  = blockIdx.z;
    const int i0  = ih * 256;
    const int k0g = kc * KC;
    const int beg = g_off[a];
    const int n   = g_off[a + 1] - beg;

    __shared__ float As[16][KC];       // P rows [m][k_local]   8 KB
    __shared__ float Bs[2][16][256];   // W subchunks [k][i]   32 KB

    const int t  = threadIdx.x;        // 0..255
    const int ti = t & 31;
    const int tm = t >> 5;             // warp-uniform m-group
    const int ia = ti * 4;
    const int ib = ti * 4 + 128;

    // this thread's W row (one row per thread, k window of this CTA)
    const float* Wrow = W + (size_t)a * F * F + (size_t)(i0 + t) * F + k0g;

    const int mS = t >> 4;             // staging: P row 0..15
    const int c4 = t & 15;             // staging: float4 lane (x2)

    // prefetch W subchunk 0 (16 k values = 4 float4 per thread-row)
    float4 w0 = *(const float4*)(Wrow + 0);
    float4 w1 = *(const float4*)(Wrow + 4);
    float4 w2 = *(const float4*)(Wrow + 8);
    float4 w3 = *(const float4*)(Wrow + 12);

    // stage 16 P rows (local K window)
    {
        const int mi = (m0 + mS < n) ? (m0 + mS) : m0;   // clamp; never written out
        const float* src = g_p_embed + (size_t)g_perm[beg + mi] * F + k0g;
        float4 p0 = *(const float4*)(src + c4 * 4);
        float4 p1 = *(const float4*)(src + (c4 + 16) * 4);
        *(float4*)&As[mS][c4 * 4]        = p0;
        *(float4*)&As[mS][(c4 + 16) * 4] = p1;
    }

    // store W subchunk 0 into buffer 0
    Bs[0][ 0][t] = w0.x; Bs[0][ 1][t] = w0.y; Bs[0][ 2][t] = w0.z; Bs[0][ 3][t] = w0.w;
    Bs[0][ 4][t] = w1.x; Bs[0][ 5][t] = w1.y; Bs[0][ 6][t] = w1.z; Bs[0][ 7][t] = w1.w;
    Bs[0][ 8][t] = w2.x; Bs[0][ 9][t] = w2.y; Bs[0][10][t] = w2.z; Bs[0][11][t] = w2.w;
    Bs[0][12][t] = w3.x; Bs[0][13][t] = w3.y; Bs[0][14][t] = w3.z; Bs[0][15][t] = w3.w;

    u64 acc2[2][4];
    #pragma unroll
    for (int r = 0; r < 2; r++)
        #pragma unroll
        for (int c = 0; c < 4; c++) acc2[r][c] = 0ULL;

    __syncthreads();   // As + Bs[0] visible

    for (int c = 0; c < KC / 16; c++) {
        const int cur  = c & 1;
        const bool more = (c + 1 < KC / 16);

        // issue next subchunk's loads before compute (overlap DRAM latency)
        if (more) {
            const int kn = (c + 1) * 16;
            w0 = *(const float4*)(Wrow + kn + 0);
            w1 = *(const float4*)(Wrow + kn + 4);
            w2 = *(const float4*)(Wrow + kn + 8);
            w3 = *(const float4*)(Wrow + kn + 12);
        }

        const int kb = c * 16;
        #pragma unroll
        for (int kk = 0; kk < 16; kk++) {
            u64 a0d, a1d;
            DUP2(a0d, As[tm * 2 + 0][kb + kk]);
            DUP2(a1d, As[tm * 2 + 1][kb + kk]);
            ulonglong2 bp0 = *(const ulonglong2*)&Bs[cur][kk][ia];
            ulonglong2 bp1 = *(const ulonglong2*)&Bs[cur][kk][ib];
            FMA2(acc2[0][0], a0d, bp0.x); FMA2(acc2[0][1], a0d, bp0.y);
            FMA2(acc2[0][2], a0d, bp1.x); FMA2(acc2[0][3], a0d, bp1.y);
            FMA2(acc2[1][0], a1d, bp0.x); FMA2(acc2[1][1], a1d, bp0.y);
            FMA2(acc2[1][2], a1d, bp1.x); FMA2(acc2[1][3], a1d, bp1.y);
        }

        if (more) {
            const int nb = cur ^ 1;
            Bs[nb][ 0][t] = w0.x; Bs[nb][ 1][t] = w0.y; Bs[nb][ 2][t] = w0.z; Bs[nb][ 3][t] = w0.w;
            Bs[nb][ 4][t] = w1.x; Bs[nb][ 5][t] = w1.y; Bs[nb][ 6][t] = w1.z; Bs[nb][ 7][t] = w1.w;
            Bs[nb][ 8][t] = w2.x; Bs[nb][ 9][t] = w2.y; Bs[nb][10][t] = w2.z; Bs[nb][11][t] = w2.w;
            Bs[nb][12][t] = w3.x; Bs[nb][13][t] = w3.y; Bs[nb][14][t] = w3.z; Bs[nb][15][t] = w3.w;
        }
        __syncthreads();   // buffer flip
    }

    // accumulate partials into output
    #pragma unroll
    for (int r = 0; r < 2; r++) {
        const int m = m0 + tm * 2 + r;
        if (m < n) {
            float* obase = dout + (size_t)g_perm[beg + m] * F + i0;
            float lo, hi;
            UNPK(lo, hi, acc2[r][0]); atomicAdd(obase + ia + 0, lo); atomicAdd(obase + ia + 1, hi);
            UNPK(lo, hi, acc2[r][1]); atomicAdd(obase + ia + 2, lo); atomicAdd(obase + ia + 3, hi);
            UNPK(lo, hi, acc2[r][2]); atomicAdd(obase + ib + 0, lo); atomicAdd(obase + ib + 1, hi);
            UNPK(lo, hi, acc2[r][3]); atomicAdd(obase + ib + 2, lo); atomicAdd(obase + ib + 3, hi);
        }
    }
}

// ---------------- launch (serial, capture-safe) ----------------
extern "C" void kernel_launch(void* const* d_in, const int* in_sizes, int n_in,
                              void* d_out, int out_size)
{
    const float* pre   = (const float*)d_in[0];
    const float* eff   = (const float*)d_in[1];
    const int*   act   = (const int*)  d_in[2];
    const float* W     = (const float*)d_in[3];
    const float* pw    = (const float*)d_in[4];
    const float* pb    = (const float*)d_in[5];
    const float* ew    = (const float*)d_in[6];
    const float* eb    = (const float*)d_in[7];
    const float* gamma = (const float*)d_in[8];
    const float* beta  = (const float*)d_in[9];
    float* out = (float*)d_out;

    k_zero<<<(BATCH * F) / (256 * 4), 256>>>(out);   // out first half only
    k_group<<<1, 256>>>(act);
    k_reduce_gn<<<dim3(BATCH, 2), 128>>>(pre, eff, gamma, beta);
    k_embed<<<dim3(F / 64, BATCH / 128, 2), 256>>>(pw, pb, ew, eb, out);
    k_action<<<dim3(256, 4, 2), 256>>>(W, out);
}